// round 1
// baseline (speedup 1.0000x reference)
#include <cuda_runtime.h>
#include <cstdint>

// Problem constants
#define BATCH 4
#define NSEQ  2048
#define DIM   512
#define HID   512
#define NEXP  16
#define ODIM  128

// Tiling
#define BM 128      // n-rows per CTA
#define HC 128      // hidden chunk width
#define BK 32       // K tile

// SMEM strides (floats) chosen for conflict-free fragment access
#define XS_STRIDE 36    // bank = 4g + tig  -> unique across warp
#define WS_STRIDE 136   // bank = 8tig + g  -> unique across warp
#define HS_STRIDE 132   // bank = 4g + tig  -> unique across warp

#define XS_OFF 0
#define WS_OFF (128 * XS_STRIDE)                 // 4608
#define HS_OFF (WS_OFF + 32 * WS_STRIDE)         // 8960
#define SMEM_FLOATS (HS_OFF + 128 * HS_STRIDE)   // 25856 floats = 103424 B

// Round fp32 -> tf32 (round-to-nearest on bit 13; tensor core truncates low 13 bits)
__device__ __forceinline__ uint32_t f2tf(float f) {
    return __float_as_uint(f) + 0x1000u;
}

__device__ __forceinline__ void mma_tf32(float c[4], const uint32_t a[4], const uint32_t b[2]) {
    asm volatile(
        "mma.sync.aligned.m16n8k8.row.col.f32.tf32.tf32.f32 "
        "{%0,%1,%2,%3}, {%4,%5,%6,%7}, {%8,%9}, {%0,%1,%2,%3};"
        : "+f"(c[0]), "+f"(c[1]), "+f"(c[2]), "+f"(c[3])
        : "r"(a[0]), "r"(a[1]), "r"(a[2]), "r"(a[3]), "r"(b[0]), "r"(b[1]));
}

__device__ __forceinline__ float gelu_exact(float v) {
    return 0.5f * v * (1.0f + erff(v * 0.70710678118654752440f));
}

extern __shared__ float smem[];

__global__ __launch_bounds__(512, 1)
void experts_fused_kernel(const float* __restrict__ x,
                          const float* __restrict__ w1,
                          const float* __restrict__ w2,
                          float* __restrict__ out)
{
    float* xs = smem + XS_OFF;   // [128][36]  x k-tile (tf32 bits)
    float* ws = smem + WS_OFF;   // [32][136]  w1/w2 k-tile (tf32 bits)
    float* hs = smem + HS_OFF;   // [128][132] gelu(hidden) chunk (tf32 bits)

    const int nt = blockIdx.x;   // 0..15
    const int e  = blockIdx.y;   // 0..15
    const int b  = blockIdx.z;   // 0..3
    const int n0 = nt * BM;

    const float* xbase  = x  + ((size_t)(b * NSEQ + n0)) * DIM;
    const float* w1base = w1 + (size_t)e * DIM * HID;
    const float* w2base = w2 + (size_t)e * HID * ODIM;

    const int tid  = threadIdx.x;
    const int warp = tid >> 5;
    const int lane = tid & 31;
    const int g    = lane >> 2;   // group id (row within fragment)
    const int tig  = lane & 3;    // thread-in-group
    const int wm   = warp >> 2;   // 0..3
    const int wn   = warp & 3;    // 0..3
    const int m0w  = wm * 32;     // warp m-offset inside 128
    const int n0w  = wn * 32;     // warp n/o-offset inside 128

    uint32_t* xsu = (uint32_t*)xs;
    uint32_t* wsu = (uint32_t*)ws;
    uint32_t* hsu = (uint32_t*)hs;

    // out accumulator: warp tile 32x32 = 2(m16) x 4(n8) mma tiles
    float oacc[2][4][4];
    #pragma unroll
    for (int mt = 0; mt < 2; mt++)
        #pragma unroll
        for (int ot = 0; ot < 4; ot++)
            #pragma unroll
            for (int i = 0; i < 4; i++) oacc[mt][ot][i] = 0.0f;

    for (int hc = 0; hc < HID / HC; hc++) {
        // ---------------- Phase A: hidden chunk = x @ w1[:, hc*128 : +128] ----------------
        float hacc[2][4][4];
        #pragma unroll
        for (int mt = 0; mt < 2; mt++)
            #pragma unroll
            for (int ot = 0; ot < 4; ot++)
                #pragma unroll
                for (int i = 0; i < 4; i++) hacc[mt][ot][i] = 0.0f;

        for (int kb = 0; kb < DIM; kb += BK) {
            __syncthreads();  // previous consumers of xs/ws done

            // load x tile [128 x 32] -> xs (tf32 bits)
            #pragma unroll
            for (int s = 0; s < 2; s++) {
                int i  = tid + s * 512;
                int r  = i >> 3;
                int c4 = (i & 7) << 2;
                float4 v = *(const float4*)(xbase + (size_t)r * DIM + kb + c4);
                uint32_t* dst = xsu + r * XS_STRIDE + c4;
                uint4 u = make_uint4(f2tf(v.x), f2tf(v.y), f2tf(v.z), f2tf(v.w));
                *(uint4*)dst = u;
            }
            // load w1 tile [32 x 128] -> ws (tf32 bits)
            #pragma unroll
            for (int s = 0; s < 2; s++) {
                int i  = tid + s * 512;
                int r  = i >> 5;
                int c4 = (i & 31) << 2;
                float4 v = *(const float4*)(w1base + (size_t)(kb + r) * HID + hc * HC + c4);
                uint32_t* dst = wsu + r * WS_STRIDE + c4;
                uint4 u = make_uint4(f2tf(v.x), f2tf(v.y), f2tf(v.z), f2tf(v.w));
                *(uint4*)dst = u;
            }
            __syncthreads();

            #pragma unroll
            for (int kk = 0; kk < 4; kk++) {
                uint32_t a[2][4], bb[4][2];
                #pragma unroll
                for (int mt = 0; mt < 2; mt++) {
                    int r = m0w + mt * 16 + g;
                    int c = kk * 8 + tig;
                    a[mt][0] = xsu[r * XS_STRIDE + c];
                    a[mt][1] = xsu[(r + 8) * XS_STRIDE + c];
                    a[mt][2] = xsu[r * XS_STRIDE + c + 4];
                    a[mt][3] = xsu[(r + 8) * XS_STRIDE + c + 4];
                }
                #pragma unroll
                for (int ot = 0; ot < 4; ot++) {
                    int col = n0w + ot * 8 + g;
                    bb[ot][0] = wsu[(kk * 8 + tig) * WS_STRIDE + col];
                    bb[ot][1] = wsu[(kk * 8 + tig + 4) * WS_STRIDE + col];
                }
                #pragma unroll
                for (int mt = 0; mt < 2; mt++)
                    #pragma unroll
                    for (int ot = 0; ot < 4; ot++)
                        mma_tf32(hacc[mt][ot], a[mt], bb[ot]);
            }
        }

        // ---------------- GELU + stage hidden chunk to smem ----------------
        __syncthreads();  // all mma reads of ws done before hs overwrite is irrelevant; protects hs readers from prior phase B
        #pragma unroll
        for (int mt = 0; mt < 2; mt++) {
            #pragma unroll
            for (int ot = 0; ot < 4; ot++) {
                int r0 = m0w + mt * 16 + g;
                int c  = n0w + ot * 8 + 2 * tig;
                uint2 lo = make_uint2(f2tf(gelu_exact(hacc[mt][ot][0])),
                                      f2tf(gelu_exact(hacc[mt][ot][1])));
                uint2 hi = make_uint2(f2tf(gelu_exact(hacc[mt][ot][2])),
                                      f2tf(gelu_exact(hacc[mt][ot][3])));
                *(uint2*)(hsu + r0 * HS_STRIDE + c)       = lo;
                *(uint2*)(hsu + (r0 + 8) * HS_STRIDE + c) = hi;
            }
        }
        __syncthreads();  // hs visible to all warps

        // ---------------- Phase B: out += gelu(hidden) @ w2[hc*128 : +128, :] ----------------
        for (int kb = 0; kb < HC; kb += BK) {
            if (kb) __syncthreads();  // previous ws consumers done
            // load w2 tile [32 x 128] -> ws (tf32 bits)
            #pragma unroll
            for (int s = 0; s < 2; s++) {
                int i  = tid + s * 512;
                int r  = i >> 5;
                int c4 = (i & 31) << 2;
                float4 v = *(const float4*)(w2base + (size_t)(hc * HC + kb + r) * ODIM + c4);
                uint32_t* dst = wsu + r * WS_STRIDE + c4;
                uint4 u = make_uint4(f2tf(v.x), f2tf(v.y), f2tf(v.z), f2tf(v.w));
                *(uint4*)dst = u;
            }
            __syncthreads();

            #pragma unroll
            for (int kk = 0; kk < 4; kk++) {
                uint32_t a[2][4], bb[4][2];
                #pragma unroll
                for (int mt = 0; mt < 2; mt++) {
                    int r = m0w + mt * 16 + g;
                    int c = kb + kk * 8 + tig;
                    a[mt][0] = hsu[r * HS_STRIDE + c];
                    a[mt][1] = hsu[(r + 8) * HS_STRIDE + c];
                    a[mt][2] = hsu[r * HS_STRIDE + c + 4];
                    a[mt][3] = hsu[(r + 8) * HS_STRIDE + c + 4];
                }
                #pragma unroll
                for (int ot = 0; ot < 4; ot++) {
                    int col = n0w + ot * 8 + g;
                    bb[ot][0] = wsu[(kk * 8 + tig) * WS_STRIDE + col];
                    bb[ot][1] = wsu[(kk * 8 + tig + 4) * WS_STRIDE + col];
                }
                #pragma unroll
                for (int mt = 0; mt < 2; mt++)
                    #pragma unroll
                    for (int ot = 0; ot < 4; ot++)
                        mma_tf32(oacc[mt][ot], a[mt], bb[ot]);
            }
        }
    }

    // ---------------- Epilogue: out[b][n][o][e], e innermost ----------------
    #pragma unroll
    for (int mt = 0; mt < 2; mt++) {
        #pragma unroll
        for (int ot = 0; ot < 4; ot++) {
            int n_row = n0 + m0w + mt * 16 + g;
            int ocol  = n0w + ot * 8 + 2 * tig;
            size_t base = (((size_t)b * NSEQ + n_row) * ODIM + ocol) * NEXP + e;
            out[base]                              = oacc[mt][ot][0];
            out[base + NEXP]                       = oacc[mt][ot][1];
            out[base + (size_t)8 * ODIM * NEXP]        = oacc[mt][ot][2];
            out[base + (size_t)8 * ODIM * NEXP + NEXP] = oacc[mt][ot][3];
        }
    }
}

extern "C" void kernel_launch(void* const* d_in, const int* in_sizes, int n_in,
                              void* d_out, int out_size) {
    const float* x  = (const float*)d_in[0];
    const float* w1 = (const float*)d_in[1];
    const float* w2 = (const float*)d_in[2];
    float* out = (float*)d_out;

    (void)in_sizes; (void)n_in; (void)out_size;

    size_t smem_bytes = SMEM_FLOATS * sizeof(float);  // 103424
    cudaFuncSetAttribute(experts_fused_kernel,
                         cudaFuncAttributeMaxDynamicSharedMemorySize,
                         (int)smem_bytes);

    dim3 grid(NSEQ / BM, NEXP, BATCH);  // (16, 16, 4)
    experts_fused_kernel<<<grid, 512, smem_bytes>>>(x, w1, w2, out);
}

// round 6
// speedup vs baseline: 1.1104x; 1.1104x over previous
#include <cuda_runtime.h>
#include <cstdint>

#define BATCH 4
#define NSEQ  2048
#define DIM   512
#define HID   512
#define NEXP  16
#define ODIM  128
#define BM    128
#define HC    128

// SMEM strides (floats), all rows 16B-aligned, conflict-free for fragment reads
#define XS_ST 36
#define WS_ST 136
#define HS_ST 132
#define XS_SZ (128 * XS_ST)   // per stage
#define WS_SZ (32 * WS_ST)
#define N_STG 3

#define XS_OFF 0
#define WS_OFF (N_STG * XS_SZ)
#define HS_OFF (WS_OFF + N_STG * WS_SZ)
#define SMEM_FLOATS (HS_OFF + 128 * HS_ST)
#define SMEM_BYTES (SMEM_FLOATS * 4)   // 175104

// Pre-rounded (tf32) copies of inputs
__device__ float g_xr [BATCH * NSEQ * DIM];   // 16 MB
__device__ float g_w1r[NEXP * DIM * HID];     // 16 MB
__device__ float g_w2r[NEXP * HID * ODIM];    //  4 MB

__device__ __forceinline__ uint32_t f2tf(float f) { return __float_as_uint(f) + 0x1000u; }

__device__ __forceinline__ uint32_t smem_u32(const void* p) {
    uint32_t a;
    asm("{ .reg .u64 t; cvta.to.shared.u64 t, %1; cvt.u32.u64 %0, t; }" : "=r"(a) : "l"(p));
    return a;
}

#define CP16(dst, src) \
    asm volatile("cp.async.cg.shared.global [%0], [%1], 16;" :: "r"(dst), "l"(src) : "memory")
#define CP_COMMIT() asm volatile("cp.async.commit_group;" ::: "memory")
#define CP_WAIT(n)  asm volatile("cp.async.wait_group %0;" :: "n"(n) : "memory")

__device__ __forceinline__ void mma_tf32(float c[4], const uint32_t a[4], const uint32_t b[2]) {
    asm volatile(
        "mma.sync.aligned.m16n8k8.row.col.f32.tf32.tf32.f32 "
        "{%0,%1,%2,%3}, {%4,%5,%6,%7}, {%8,%9}, {%0,%1,%2,%3};"
        : "+f"(c[0]), "+f"(c[1]), "+f"(c[2]), "+f"(c[3])
        : "r"(a[0]), "r"(a[1]), "r"(a[2]), "r"(a[3]), "r"(b[0]), "r"(b[1]));
}

__device__ __forceinline__ float gelu_exact(float v) {
    return 0.5f * v * (1.0f + erff(v * 0.70710678118654752440f));
}

// ---------------- prep: round fp32 -> tf32 bits (elementwise) ----------------
__global__ void prep_round(const float* __restrict__ src, float* __restrict__ dst, int n4) {
    int i = blockIdx.x * blockDim.x + threadIdx.x;
    if (i < n4) {
        float4 v = ((const float4*)src)[i];
        uint4 u = make_uint4(f2tf(v.x), f2tf(v.y), f2tf(v.z), f2tf(v.w));
        ((uint4*)dst)[i] = u;
    }
}

// ---------------- main fused kernel ----------------
extern __shared__ float smem[];

__global__ __launch_bounds__(512, 1)
void experts_fused_kernel(float* __restrict__ out)
{
    const uint32_t sb    = smem_u32(smem);
    const uint32_t sb_xs = sb + XS_OFF * 4;
    const uint32_t sb_ws = sb + WS_OFF * 4;
    uint32_t* hsu = (uint32_t*)(smem + HS_OFF);
    uint32_t* xsu_all = (uint32_t*)(smem + XS_OFF);
    uint32_t* wsu_all = (uint32_t*)(smem + WS_OFF);

    const int nt = blockIdx.x;   // 0..15
    const int e  = blockIdx.y;   // 0..15
    const int b  = blockIdx.z;   // 0..3
    const int n0 = nt * BM;

    const float* xb  = g_xr  + (size_t)(b * NSEQ + n0) * DIM;
    const float* w1e = g_w1r + (size_t)e * DIM * HID;
    const float* w2e = g_w2r + (size_t)e * HID * ODIM;

    const int tid  = threadIdx.x;
    const int warp = tid >> 5;
    const int lane = tid & 31;
    const int g    = lane >> 2;
    const int tig  = lane & 3;
    const int wm   = warp >> 2;
    const int wn   = warp & 3;
    const int m0w  = wm * 32;
    const int n0w  = wn * 32;

    // per-thread load coordinates (hoisted)
    const int xr0 = tid >> 3,          xc0 = (tid & 7) << 2;          // + i*64 rows
    const int wr0 = tid >> 5,          wc0 = (tid & 31) << 2;         // + i*16 rows

    // issue cp.async for x k-tile t into stage s
    #define LOADX(t, s) do {                                                        \
        uint32_t xd = sb_xs + (s) * (XS_SZ * 4);                                    \
        CP16(xd + (xr0)      * (XS_ST*4) + xc0 * 4, xb + (size_t)(xr0)      * DIM + (t)*32 + xc0); \
        CP16(xd + (xr0 + 64) * (XS_ST*4) + xc0 * 4, xb + (size_t)(xr0 + 64) * DIM + (t)*32 + xc0); \
    } while (0)

    // issue cp.async for w1 k-tile t (hidden chunk hcI) into stage s
    #define LOADW1(t, hcI, s) do {                                                  \
        uint32_t wd = sb_ws + (s) * (WS_SZ * 4);                                    \
        CP16(wd + (wr0)      * (WS_ST*4) + wc0 * 4, w1e + (size_t)((t)*32 + wr0)      * HID + (hcI)*HC + wc0); \
        CP16(wd + (wr0 + 16) * (WS_ST*4) + wc0 * 4, w1e + (size_t)((t)*32 + wr0 + 16) * HID + (hcI)*HC + wc0); \
    } while (0)

    // issue cp.async for w2 k-tile t (hidden chunk hcI) into stage s
    #define LOADW2(t, hcI, s) do {                                                  \
        uint32_t wd = sb_ws + (s) * (WS_SZ * 4);                                    \
        CP16(wd + (wr0)      * (WS_ST*4) + wc0 * 4, w2e + (size_t)((hcI)*HC + (t)*32 + wr0)      * ODIM + wc0); \
        CP16(wd + (wr0 + 16) * (WS_ST*4) + wc0 * 4, w2e + (size_t)((hcI)*HC + (t)*32 + wr0 + 16) * ODIM + wc0); \
    } while (0)

    float oacc[2][4][4];
    #pragma unroll
    for (int mt = 0; mt < 2; mt++)
        #pragma unroll
        for (int ot = 0; ot < 4; ot++)
            #pragma unroll
            for (int i = 0; i < 4; i++) oacc[mt][ot][i] = 0.0f;

    for (int hcI = 0; hcI < HID / HC; hcI++) {
        // ========== Phase A: hidden[128,128] = X @ W1[:, hcI*128:+128] ==========
        float hacc[2][4][4];
        #pragma unroll
        for (int mt = 0; mt < 2; mt++)
            #pragma unroll
            for (int ot = 0; ot < 4; ot++)
                #pragma unroll
                for (int i = 0; i < 4; i++) hacc[mt][ot][i] = 0.0f;

        // prologue: stages 0,1
        LOADX(0, 0); LOADW1(0, hcI, 0); CP_COMMIT();
        LOADX(1, 1); LOADW1(1, hcI, 1); CP_COMMIT();

        for (int t = 0; t < 16; t++) {
            const int s = t % N_STG;
            if (t < 15) { CP_WAIT(1); } else { CP_WAIT(0); }
            __syncthreads();
            if (t + 2 < 16) {
                const int s2 = (t + 2) % N_STG;
                LOADX(t + 2, s2); LOADW1(t + 2, hcI, s2); CP_COMMIT();
            }
            const uint32_t* xsu = xsu_all + s * XS_SZ;
            const uint32_t* wsu = wsu_all + s * WS_SZ;
            #pragma unroll
            for (int kk = 0; kk < 4; kk++) {
                uint32_t a[2][4], bb[4][2];
                #pragma unroll
                for (int mt = 0; mt < 2; mt++) {
                    int r = m0w + mt * 16 + g;
                    int c = kk * 8 + tig;
                    a[mt][0] = xsu[r * XS_ST + c];
                    a[mt][1] = xsu[(r + 8) * XS_ST + c];
                    a[mt][2] = xsu[r * XS_ST + c + 4];
                    a[mt][3] = xsu[(r + 8) * XS_ST + c + 4];
                }
                #pragma unroll
                for (int ot = 0; ot < 4; ot++) {
                    int col = n0w + ot * 8 + g;
                    bb[ot][0] = wsu[(kk * 8 + tig) * WS_ST + col];
                    bb[ot][1] = wsu[(kk * 8 + tig + 4) * WS_ST + col];
                }
                #pragma unroll
                for (int mt = 0; mt < 2; mt++)
                    #pragma unroll
                    for (int ot = 0; ot < 4; ot++)
                        mma_tf32(hacc[mt][ot], a[mt], bb[ot]);
            }
        }
        __syncthreads();   // all MMAs of phase A done; ws/hs safe to overwrite

        // prefetch phase-B stages 0,1 (flies during GELU)
        LOADW2(0, hcI, 0); CP_COMMIT();
        LOADW2(1, hcI, 1); CP_COMMIT();

        // ========== GELU: hacc -> hs (tf32 bits) ==========
        #pragma unroll
        for (int mt = 0; mt < 2; mt++) {
            #pragma unroll
            for (int ot = 0; ot < 4; ot++) {
                int r0 = m0w + mt * 16 + g;
                int c  = n0w + ot * 8 + 2 * tig;
                uint2 lo = make_uint2(f2tf(gelu_exact(hacc[mt][ot][0])),
                                      f2tf(gelu_exact(hacc[mt][ot][1])));
                uint2 hi = make_uint2(f2tf(gelu_exact(hacc[mt][ot][2])),
                                      f2tf(gelu_exact(hacc[mt][ot][3])));
                *(uint2*)(hsu + r0 * HS_ST + c)       = lo;
                *(uint2*)(hsu + (r0 + 8) * HS_ST + c) = hi;
            }
        }
        __syncthreads();   // hs visible

        // ========== Phase B: out += gelu(hidden) @ W2[hcI*128:+128, :] ==========
        for (int t = 0; t < 4; t++) {
            const int s = t % N_STG;
            if (t < 3) { CP_WAIT(1); } else { CP_WAIT(0); }
            __syncthreads();
            if (t + 2 < 4) { LOADW2(t + 2, hcI, (t + 2) % N_STG); CP_COMMIT(); }
            const uint32_t* wsu = wsu_all + s * WS_SZ;
            #pragma unroll
            for (int kk = 0; kk < 4; kk++) {
                uint32_t a[2][4], bb[4][2];
                #pragma unroll
                for (int mt = 0; mt < 2; mt++) {
                    int r = m0w + mt * 16 + g;
                    int c = t * 32 + kk * 8 + tig;
                    a[mt][0] = hsu[r * HS_ST + c];
                    a[mt][1] = hsu[(r + 8) * HS_ST + c];
                    a[mt][2] = hsu[r * HS_ST + c + 4];
                    a[mt][3] = hsu[(r + 8) * HS_ST + c + 4];
                }
                #pragma unroll
                for (int ot = 0; ot < 4; ot++) {
                    int col = n0w + ot * 8 + g;
                    bb[ot][0] = wsu[(kk * 8 + tig) * WS_ST + col];
                    bb[ot][1] = wsu[(kk * 8 + tig + 4) * WS_ST + col];
                }
                #pragma unroll
                for (int mt = 0; mt < 2; mt++)
                    #pragma unroll
                    for (int ot = 0; ot < 4; ot++)
                        mma_tf32(oacc[mt][ot], a[mt], bb[ot]);
            }
        }
        __syncthreads();   // phase B MMAs done before next hc overwrites ws/hs
    }

    // ========== Epilogue: out[b][n][o][e], e innermost ==========
    #pragma unroll
    for (int mt = 0; mt < 2; mt++) {
        #pragma unroll
        for (int ot = 0; ot < 4; ot++) {
            int n_row = n0 + m0w + mt * 16 + g;
            int ocol  = n0w + ot * 8 + 2 * tig;
            size_t base = (((size_t)b * NSEQ + n_row) * ODIM + ocol) * NEXP + e;
            out[base]                                  = oacc[mt][ot][0];
            out[base + NEXP]                           = oacc[mt][ot][1];
            out[base + (size_t)8 * ODIM * NEXP]        = oacc[mt][ot][2];
            out[base + (size_t)8 * ODIM * NEXP + NEXP] = oacc[mt][ot][3];
        }
    }
}

// ---------------- launch ----------------
extern "C" void kernel_launch(void* const* d_in, const int* in_sizes, int n_in,
                              void* d_out, int out_size) {
    const float* x  = (const float*)d_in[0];
    const float* w1 = (const float*)d_in[1];
    const float* w2 = (const float*)d_in[2];
    float* out = (float*)d_out;
    (void)in_sizes; (void)n_in; (void)out_size;

    cudaFuncSetAttribute(experts_fused_kernel,
                         cudaFuncAttributeMaxDynamicSharedMemorySize, SMEM_BYTES);

    float* xr;  cudaGetSymbolAddress((void**)&xr,  g_xr);
    float* w1r; cudaGetSymbolAddress((void**)&w1r, g_w1r);
    float* w2r; cudaGetSymbolAddress((void**)&w2r, g_w2r);

    const int nx  = BATCH * NSEQ * DIM / 4;   // float4 count
    const int nw1 = NEXP * DIM * HID / 4;
    const int nw2 = NEXP * HID * ODIM / 4;
    prep_round<<<(nx  + 255) / 256, 256>>>(x,  xr,  nx);
    prep_round<<<(nw1 + 255) / 256, 256>>>(w1, w1r, nw1);
    prep_round<<<(nw2 + 255) / 256, 256>>>(w2, w2r, nw2);

    dim3 grid(NSEQ / BM, NEXP, BATCH);  // (16,16,4)
    experts_fused_kernel<<<grid, 512, SMEM_BYTES>>>(out);
}

// round 9
// speedup vs baseline: 2.0282x; 1.8265x over previous
#include <cuda_runtime.h>
#include <cuda_fp16.h>
#include <cstdint>

#define BATCH 4
#define NSEQ  2048
#define DIM   512
#define HID   512
#define NEXP  16
#define ODIM  128
#define BM    128
#define HC    128

// fp16 staged copies
__device__ __half g_xh [BATCH * NSEQ * DIM];   // [b][n][d]
__device__ __half g_w1t[NEXP * HID * DIM];     // [e][h][d]  (N-major for GEMM1 B)
__device__ __half g_w2t[NEXP * ODIM * HID];    // [e][o][h]  (N-major for GEMM2 B)

// ---- SMEM layout (bytes) ----
#define XROW 80          // 32 halves + 16B pad: ldmatrix conflict-free
#define HROW 272         // 128 halves + 16B pad
#define XSB  10240       // 128 rows x 80B
#define WSB  10240
#define N_STG 4
#define XS_OFF 0
#define WS_OFF (N_STG * XSB)              // 40960
#define HS_OFF (WS_OFF + N_STG * WSB)     // 81920
#define SMEM_BYTES (HS_OFF + 128 * HROW + 64)  // 116800 (tail pad)

__device__ __forceinline__ uint32_t smem_u32(const void* p) {
    uint32_t a;
    asm("{ .reg .u64 t; cvta.to.shared.u64 t, %1; cvt.u32.u64 %0, t; }" : "=r"(a) : "l"(p));
    return a;
}

#define CP16(dst, src) \
    asm volatile("cp.async.cg.shared.global [%0], [%1], 16;" :: "r"(dst), "l"(src) : "memory")
#define CP_COMMIT() asm volatile("cp.async.commit_group;" ::: "memory")
#define CP_WAIT(n)  asm volatile("cp.async.wait_group %0;" :: "n"(n) : "memory")

#define LDSM4(r0, r1, r2, r3, addr) \
    asm volatile("ldmatrix.sync.aligned.m8n8.x4.shared.b16 {%0,%1,%2,%3}, [%4];" \
        : "=r"(r0), "=r"(r1), "=r"(r2), "=r"(r3) : "r"(addr))

__device__ __forceinline__ void mma_f16(float c[4], const uint32_t a[4], uint32_t b0, uint32_t b1) {
    asm volatile(
        "mma.sync.aligned.m16n8k16.row.col.f32.f16.f16.f32 "
        "{%0,%1,%2,%3}, {%4,%5,%6,%7}, {%8,%9}, {%0,%1,%2,%3};"
        : "+f"(c[0]), "+f"(c[1]), "+f"(c[2]), "+f"(c[3])
        : "r"(a[0]), "r"(a[1]), "r"(a[2]), "r"(a[3]), "r"(b0), "r"(b1));
}

__device__ __forceinline__ float gelu_exact(float v) {
    return 0.5f * v * (1.0f + erff(v * 0.70710678118654752440f));
}

// ---------------- prep kernels ----------------
__global__ void prep_x(const float* __restrict__ src, int n4) {
    int i = blockIdx.x * blockDim.x + threadIdx.x;
    if (i < n4) {
        float4 v = ((const float4*)src)[i];
        ((__half2*)g_xh)[i * 2]     = __floats2half2_rn(v.x, v.y);
        ((__half2*)g_xh)[i * 2 + 1] = __floats2half2_rn(v.z, v.w);
    }
}

__global__ void prep_w1t(const float* __restrict__ w1) {
    __shared__ float t[32][33];
    int d0 = blockIdx.x * 32, h0 = blockIdx.y * 32, e = blockIdx.z;
    const float* src = w1 + (size_t)e * DIM * HID;
    __half*      dst = g_w1t + (size_t)e * HID * DIM;
    int tx = threadIdx.x, ty = threadIdx.y;
    #pragma unroll
    for (int k = 0; k < 4; k++)
        t[ty + k*8][tx] = src[(size_t)(d0 + ty + k*8) * HID + h0 + tx];
    __syncthreads();
    #pragma unroll
    for (int k = 0; k < 4; k++)
        dst[(size_t)(h0 + ty + k*8) * DIM + d0 + tx] = __float2half_rn(t[tx][ty + k*8]);
}

__global__ void prep_w2t(const float* __restrict__ w2) {
    __shared__ float t[32][33];
    int h0 = blockIdx.x * 32, o0 = blockIdx.y * 32, e = blockIdx.z;
    const float* src = w2 + (size_t)e * HID * ODIM;
    __half*      dst = g_w2t + (size_t)e * ODIM * HID;
    int tx = threadIdx.x, ty = threadIdx.y;
    #pragma unroll
    for (int k = 0; k < 4; k++)
        t[ty + k*8][tx] = src[(size_t)(h0 + ty + k*8) * ODIM + o0 + tx];
    __syncthreads();
    #pragma unroll
    for (int k = 0; k < 4; k++)
        dst[(size_t)(o0 + ty + k*8) * HID + h0 + tx] = __float2half_rn(t[tx][ty + k*8]);
}

// ---------------- main fused kernel ----------------
extern __shared__ char smem[];

__global__ __launch_bounds__(512, 1)
void experts_fused_kernel(float* __restrict__ out)
{
    const uint32_t sb = smem_u32(smem);

    const int nt = blockIdx.x;   // 0..15
    const int e  = blockIdx.y;   // 0..15
    const int b  = blockIdx.z;   // 0..3
    const int n0 = nt * BM;

    const __half* xb  = g_xh  + (size_t)(b * NSEQ + n0) * DIM;
    const __half* w1e = g_w1t + (size_t)e * HID * DIM;
    const __half* w2e = g_w2t + (size_t)e * ODIM * HID;

    const int tid  = threadIdx.x;
    const int warp = tid >> 5;
    const int lane = tid & 31;
    const int g    = lane >> 2;
    const int tig  = lane & 3;
    const int wm   = warp >> 2;   // 0..3
    const int wn   = warp & 3;    // 0..3
    const int m0w  = wm * 32;
    const int n0w  = wn * 32;

    // cp.async coords: one 16B chunk per thread per tile
    const int ld_row = tid >> 2;            // 0..127
    const int ld_ch  = tid & 3;             // 16B chunk
    const uint32_t ld_dst = (uint32_t)(ld_row * XROW + ld_ch * 16);
    const int ld_src = ld_ch * 8;           // halves

    // ldmatrix per-lane offsets (relative to stage base)
    const uint32_t xa_off = (uint32_t)((m0w + (lane & 15)) * XROW + (lane >> 4) * 16);
    const uint32_t wb_off = (uint32_t)((n0w + (lane & 7) + ((lane >> 4) & 1) * 8) * XROW
                                       + ((lane >> 3) & 1) * 16);
    const uint32_t ha_off = (uint32_t)(HS_OFF + (m0w + (lane & 15)) * HROW + (lane >> 4) * 16);

    #define LOADX(t, s) do {                                                           \
        CP16(sb + XS_OFF + (s)*XSB + ld_dst, xb + (size_t)ld_row * DIM + (t)*32 + ld_src); \
    } while (0)
    #define LOADW1(t, hcI, s) do {                                                     \
        CP16(sb + WS_OFF + (s)*WSB + ld_dst,                                           \
             w1e + (size_t)((hcI)*HC + ld_row) * DIM + (t)*32 + ld_src);               \
    } while (0)
    #define LOADW2(t, hcI, s) do {                                                     \
        CP16(sb + WS_OFF + (s)*WSB + ld_dst,                                           \
             w2e + (size_t)ld_row * HID + (hcI)*HC + (t)*32 + ld_src);                 \
    } while (0)

    float oacc[2][4][4];
    #pragma unroll
    for (int mt = 0; mt < 2; mt++)
        #pragma unroll
        for (int ot = 0; ot < 4; ot++)
            #pragma unroll
            for (int i = 0; i < 4; i++) oacc[mt][ot][i] = 0.0f;

    // one k16 step: 4 LDSM.x4 + 8 MMA
    #define MMA_STEP(acc, abase, astride, bbase, kbyte) do {                           \
        uint32_t a0[4], a1[4], b0[4], b1[4];                                           \
        LDSM4(a0[0], a0[1], a0[2], a0[3], (abase) + (kbyte));                          \
        LDSM4(a1[0], a1[1], a1[2], a1[3], (abase) + (astride) + (kbyte));              \
        LDSM4(b0[0], b0[1], b0[2], b0[3], (bbase) + (kbyte));                          \
        LDSM4(b1[0], b1[1], b1[2], b1[3], (bbase) + 1280 + (kbyte));                   \
        mma_f16(acc[0][0], a0, b0[0], b0[1]);                                          \
        mma_f16(acc[0][1], a0, b0[2], b0[3]);                                          \
        mma_f16(acc[0][2], a0, b1[0], b1[1]);                                          \
        mma_f16(acc[0][3], a0, b1[2], b1[3]);                                          \
        mma_f16(acc[1][0], a1, b0[0], b0[1]);                                          \
        mma_f16(acc[1][1], a1, b0[2], b0[3]);                                          \
        mma_f16(acc[1][2], a1, b1[0], b1[1]);                                          \
        mma_f16(acc[1][3], a1, b1[2], b1[3]);                                          \
    } while (0)

    for (int hcI = 0; hcI < HID / HC; hcI++) {
        // ========== Phase A: hidden[128,128] = X @ W1chunk ==========
        float hacc[2][4][4];
        #pragma unroll
        for (int mt = 0; mt < 2; mt++)
            #pragma unroll
            for (int ot = 0; ot < 4; ot++)
                #pragma unroll
                for (int i = 0; i < 4; i++) hacc[mt][ot][i] = 0.0f;

        // prologue: 3 stages in flight
        LOADX(0, 0); LOADW1(0, hcI, 0); CP_COMMIT();
        LOADX(1, 1); LOADW1(1, hcI, 1); CP_COMMIT();
        LOADX(2, 2); LOADW1(2, hcI, 2); CP_COMMIT();

        for (int t = 0; t < 16; t++) {
            const int s = t & 3;
            if (t < 14)      { CP_WAIT(2); }
            else if (t == 14){ CP_WAIT(1); }
            else             { CP_WAIT(0); }
            __syncthreads();   // cross-thread visibility of stage s
            if (t + 3 < 16) {
                const int s3 = (t + 3) & 3;
                LOADX(t + 3, s3); LOADW1(t + 3, hcI, s3); CP_COMMIT();
            }
            const uint32_t xa = sb + XS_OFF + s * XSB + xa_off;
            const uint32_t wa = sb + WS_OFF + s * WSB + wb_off;
            MMA_STEP(hacc, xa, 1280, wa, 0);
            MMA_STEP(hacc, xa, 1280, wa, 32);
        }
        __syncthreads();   // phase-A reads done; ws/hs free to overwrite

        // prefetch ALL 4 phase-B tiles (one stage each); they fly during GELU
        LOADW2(0, hcI, 0); CP_COMMIT();
        LOADW2(1, hcI, 1); CP_COMMIT();
        LOADW2(2, hcI, 2); CP_COMMIT();
        LOADW2(3, hcI, 3); CP_COMMIT();

        // ========== GELU: hacc -> hs (fp16) ==========
        #pragma unroll
        for (int mt = 0; mt < 2; mt++) {
            #pragma unroll
            for (int ot = 0; ot < 4; ot++) {
                int r0 = m0w + mt * 16 + g;
                int c  = n0w + ot * 8 + 2 * tig;
                __half2 lo = __floats2half2_rn(gelu_exact(hacc[mt][ot][0]),
                                               gelu_exact(hacc[mt][ot][1]));
                __half2 hi = __floats2half2_rn(gelu_exact(hacc[mt][ot][2]),
                                               gelu_exact(hacc[mt][ot][3]));
                *(__half2*)(smem + HS_OFF + r0 * HROW + c * 2)       = lo;
                *(__half2*)(smem + HS_OFF + (r0 + 8) * HROW + c * 2) = hi;
            }
        }
        CP_WAIT(0);        // all W2 stages resident (this thread's copies)
        __syncthreads();   // hs + all threads' W2 copies visible to everyone

        // ========== Phase B: out += gelu(hidden) @ W2chunk (no further waits) ==========
        #pragma unroll
        for (int t = 0; t < 4; t++) {
            const uint32_t ha = sb + ha_off + t * 64;
            const uint32_t wa = sb + WS_OFF + t * WSB + wb_off;
            MMA_STEP(oacc, ha, 16 * HROW, wa, 0);
            MMA_STEP(oacc, ha, 16 * HROW, wa, 32);
        }
        __syncthreads();   // phase-B MMAs done before next hc overwrites ws/hs
    }

    // ========== Epilogue: out[b][n][o][e], e innermost ==========
    #pragma unroll
    for (int mt = 0; mt < 2; mt++) {
        #pragma unroll
        for (int ot = 0; ot < 4; ot++) {
            int n_row = n0 + m0w + mt * 16 + g;
            int ocol  = n0w + ot * 8 + 2 * tig;
            size_t base = (((size_t)b * NSEQ + n_row) * ODIM + ocol) * NEXP + e;
            out[base]                                  = oacc[mt][ot][0];
            out[base + NEXP]                           = oacc[mt][ot][1];
            out[base + (size_t)8 * ODIM * NEXP]        = oacc[mt][ot][2];
            out[base + (size_t)8 * ODIM * NEXP + NEXP] = oacc[mt][ot][3];
        }
    }
}

// ---------------- launch ----------------
extern "C" void kernel_launch(void* const* d_in, const int* in_sizes, int n_in,
                              void* d_out, int out_size) {
    const float* x  = (const float*)d_in[0];
    const float* w1 = (const float*)d_in[1];
    const float* w2 = (const float*)d_in[2];
    float* out = (float*)d_out;
    (void)in_sizes; (void)n_in; (void)out_size;

    cudaFuncSetAttribute(experts_fused_kernel,
                         cudaFuncAttributeMaxDynamicSharedMemorySize, SMEM_BYTES);

    const int nx = BATCH * NSEQ * DIM / 4;
    prep_x<<<(nx + 255) / 256, 256>>>(x, nx);
    dim3 tb(32, 8, 1);
    prep_w1t<<<dim3(DIM/32, HID/32, NEXP), tb>>>(w1);
    prep_w2t<<<dim3(HID/32, ODIM/32, NEXP), tb>>>(w2);

    dim3 grid(NSEQ / BM, NEXP, BATCH);  // (16,16,4)
    experts_fused_kernel<<<grid, 512, SMEM_BYTES>>>(out);
}

// round 10
// speedup vs baseline: 2.0602x; 1.0158x over previous
#include <cuda_runtime.h>
#include <cuda_fp16.h>
#include <cstdint>

#define BATCH 4
#define NSEQ  2048
#define DIM   512
#define HID   512
#define NEXP  16
#define ODIM  128
#define BM    64
#define HC    128
#define KT    64

// fp16 staged copies
__device__ __half g_xh [BATCH * NSEQ * DIM];   // [b][n][d]
__device__ __half g_w1t[NEXP * HID * DIM];     // [e][h][d]  (N-major for GEMM1 B)
__device__ __half g_w2t[NEXP * ODIM * HID];    // [e][o][h]  (N-major for GEMM2 B)

// ---- SMEM layout (bytes) ----
#define XROW 144         // 64 halves + 16B pad: ldmatrix conflict-free (36 banks/row -> 4r mod 32)
#define HROW 272         // 128 halves + 16B pad
#define XSB  (64 * XROW)     // 9216
#define WSB  (128 * XROW)    // 18432
#define N_STG 3
#define XS_OFF 0
#define WS_OFF (N_STG * XSB)              // 27648
#define HS_OFF (WS_OFF + N_STG * WSB)     // 82944
#define SMEM_BYTES (HS_OFF + BM * HROW + 64)   // 100416

__device__ __forceinline__ uint32_t smem_u32(const void* p) {
    uint32_t a;
    asm("{ .reg .u64 t; cvta.to.shared.u64 t, %1; cvt.u32.u64 %0, t; }" : "=r"(a) : "l"(p));
    return a;
}

#define CP16(dst, src) \
    asm volatile("cp.async.cg.shared.global [%0], [%1], 16;" :: "r"(dst), "l"(src) : "memory")
#define CP_COMMIT() asm volatile("cp.async.commit_group;" ::: "memory")
#define CP_WAIT(n)  asm volatile("cp.async.wait_group %0;" :: "n"(n) : "memory")

#define LDSM4(r0, r1, r2, r3, addr) \
    asm volatile("ldmatrix.sync.aligned.m8n8.x4.shared.b16 {%0,%1,%2,%3}, [%4];" \
        : "=r"(r0), "=r"(r1), "=r"(r2), "=r"(r3) : "r"(addr))

__device__ __forceinline__ void mma_f16(float c[4], const uint32_t a[4], uint32_t b0, uint32_t b1) {
    asm volatile(
        "mma.sync.aligned.m16n8k16.row.col.f32.f16.f16.f32 "
        "{%0,%1,%2,%3}, {%4,%5,%6,%7}, {%8,%9}, {%0,%1,%2,%3};"
        : "+f"(c[0]), "+f"(c[1]), "+f"(c[2]), "+f"(c[3])
        : "r"(a[0]), "r"(a[1]), "r"(a[2]), "r"(a[3]), "r"(b0), "r"(b1));
}

__device__ __forceinline__ float gelu_exact(float v) {
    return 0.5f * v * (1.0f + erff(v * 0.70710678118654752440f));
}

// ---------------- prep kernels ----------------
__global__ void prep_x(const float* __restrict__ src, int n4) {
    int i = blockIdx.x * blockDim.x + threadIdx.x;
    if (i < n4) {
        float4 v = ((const float4*)src)[i];
        ((__half2*)g_xh)[i * 2]     = __floats2half2_rn(v.x, v.y);
        ((__half2*)g_xh)[i * 2 + 1] = __floats2half2_rn(v.z, v.w);
    }
}

__global__ void prep_w1t(const float* __restrict__ w1) {
    __shared__ float t[32][33];
    int d0 = blockIdx.x * 32, h0 = blockIdx.y * 32, e = blockIdx.z;
    const float* src = w1 + (size_t)e * DIM * HID;
    __half*      dst = g_w1t + (size_t)e * HID * DIM;
    int tx = threadIdx.x, ty = threadIdx.y;
    #pragma unroll
    for (int k = 0; k < 4; k++)
        t[ty + k*8][tx] = src[(size_t)(d0 + ty + k*8) * HID + h0 + tx];
    __syncthreads();
    #pragma unroll
    for (int k = 0; k < 4; k++)
        dst[(size_t)(h0 + ty + k*8) * DIM + d0 + tx] = __float2half_rn(t[tx][ty + k*8]);
}

__global__ void prep_w2t(const float* __restrict__ w2) {
    __shared__ float t[32][33];
    int h0 = blockIdx.x * 32, o0 = blockIdx.y * 32, e = blockIdx.z;
    const float* src = w2 + (size_t)e * HID * ODIM;
    __half*      dst = g_w2t + (size_t)e * ODIM * HID;
    int tx = threadIdx.x, ty = threadIdx.y;
    #pragma unroll
    for (int k = 0; k < 4; k++)
        t[ty + k*8][tx] = src[(size_t)(h0 + ty + k*8) * ODIM + o0 + tx];
    __syncthreads();
    #pragma unroll
    for (int k = 0; k < 4; k++)
        dst[(size_t)(o0 + ty + k*8) * HID + h0 + tx] = __float2half_rn(t[tx][ty + k*8]);
}

// ---------------- main fused kernel ----------------
extern __shared__ char smem[];

__global__ __launch_bounds__(256, 2)
void experts_fused_kernel(float* __restrict__ out)
{
    const uint32_t sb = smem_u32(smem);

    const int nt = blockIdx.x;   // 0..31
    const int e  = blockIdx.y;   // 0..15
    const int b  = blockIdx.z;   // 0..3
    const int n0 = nt * BM;

    const __half* xb  = g_xh  + (size_t)(b * NSEQ + n0) * DIM;
    const __half* w1e = g_w1t + (size_t)e * HID * DIM;
    const __half* w2e = g_w2t + (size_t)e * ODIM * HID;

    const int tid  = threadIdx.x;
    const int warp = tid >> 5;
    const int lane = tid & 31;
    const int g    = lane >> 2;
    const int tig  = lane & 3;
    const int wm   = warp >> 2;   // 0..1
    const int wn   = warp & 3;    // 0..3
    const int m0w  = wm * 32;
    const int n0w  = wn * 32;

    // cp.async coords: 16B chunks; x tile 64x64h = 512 chunks (2/thr); w tile 128x64h = 1024 (4/thr)
    const int cr0 = tid >> 3;          // base row for chunk set (0..31)
    const int cc0 = (tid & 7) << 4;    // byte col in row (0..112)
    const int cs0 = (tid & 7) << 3;    // half col in src

    // ldmatrix per-lane offsets (relative to stage base)
    const uint32_t xa_off = (uint32_t)((m0w + (lane & 15)) * XROW + (lane >> 4) * 16);
    const uint32_t wb_off = (uint32_t)((n0w + (lane & 7) + ((lane >> 4) & 1) * 8) * XROW
                                       + ((lane >> 3) & 1) * 16);
    const uint32_t ha_off = (uint32_t)(HS_OFF + (m0w + (lane & 15)) * HROW + (lane >> 4) * 16);

    #define LOADX(t, s) do {                                                           \
        uint32_t xd = sb + XS_OFF + (s)*XSB;                                           \
        CP16(xd + (cr0)      * XROW + cc0, xb + (size_t)(cr0)      * DIM + (t)*KT + cs0); \
        CP16(xd + (cr0 + 32) * XROW + cc0, xb + (size_t)(cr0 + 32) * DIM + (t)*KT + cs0); \
    } while (0)
    #define LOADW1(t, hcI, s) do {                                                     \
        uint32_t wd = sb + WS_OFF + (s)*WSB;                                           \
        CP16(wd + (cr0)      * XROW + cc0, w1e + (size_t)((hcI)*HC + cr0)      * DIM + (t)*KT + cs0); \
        CP16(wd + (cr0 + 32) * XROW + cc0, w1e + (size_t)((hcI)*HC + cr0 + 32) * DIM + (t)*KT + cs0); \
        CP16(wd + (cr0 + 64) * XROW + cc0, w1e + (size_t)((hcI)*HC + cr0 + 64) * DIM + (t)*KT + cs0); \
        CP16(wd + (cr0 + 96) * XROW + cc0, w1e + (size_t)((hcI)*HC + cr0 + 96) * DIM + (t)*KT + cs0); \
    } while (0)
    #define LOADW2(t, hcI, s) do {                                                     \
        uint32_t wd = sb + WS_OFF + (s)*WSB;                                           \
        CP16(wd + (cr0)      * XROW + cc0, w2e + (size_t)(cr0)      * HID + (hcI)*HC + (t)*KT + cs0); \
        CP16(wd + (cr0 + 32) * XROW + cc0, w2e + (size_t)(cr0 + 32) * HID + (hcI)*HC + (t)*KT + cs0); \
        CP16(wd + (cr0 + 64) * XROW + cc0, w2e + (size_t)(cr0 + 64) * HID + (hcI)*HC + (t)*KT + cs0); \
        CP16(wd + (cr0 + 96) * XROW + cc0, w2e + (size_t)(cr0 + 96) * HID + (hcI)*HC + (t)*KT + cs0); \
    } while (0)

    float oacc[2][4][4];
    #pragma unroll
    for (int mt = 0; mt < 2; mt++)
        #pragma unroll
        for (int ot = 0; ot < 4; ot++)
            #pragma unroll
            for (int i = 0; i < 4; i++) oacc[mt][ot][i] = 0.0f;

    // one k16 step: 4 LDSM.x4 + 8 MMA. astride = 16 rows of A; B pair 2 = +16 rows (+2304B)
    #define MMA_STEP(acc, abase, astride, bbase, bstride, kbyte) do {                  \
        uint32_t a0[4], a1[4], b0[4], b1[4];                                           \
        LDSM4(a0[0], a0[1], a0[2], a0[3], (abase) + (kbyte));                          \
        LDSM4(a1[0], a1[1], a1[2], a1[3], (abase) + (astride) + (kbyte));              \
        LDSM4(b0[0], b0[1], b0[2], b0[3], (bbase) + (kbyte));                          \
        LDSM4(b1[0], b1[1], b1[2], b1[3], (bbase) + (bstride) + (kbyte));              \
        mma_f16(acc[0][0], a0, b0[0], b0[1]);                                          \
        mma_f16(acc[0][1], a0, b0[2], b0[3]);                                          \
        mma_f16(acc[0][2], a0, b1[0], b1[1]);                                          \
        mma_f16(acc[0][3], a0, b1[2], b1[3]);                                          \
        mma_f16(acc[1][0], a1, b0[0], b0[1]);                                          \
        mma_f16(acc[1][1], a1, b0[2], b0[3]);                                          \
        mma_f16(acc[1][2], a1, b1[0], b1[1]);                                          \
        mma_f16(acc[1][3], a1, b1[2], b1[3]);                                          \
    } while (0)

    for (int hcI = 0; hcI < HID / HC; hcI++) {
        // ========== Phase A: hidden[64,128] = X @ W1chunk, K=512 in 8 k64-tiles ==========
        float hacc[2][4][4];
        #pragma unroll
        for (int mt = 0; mt < 2; mt++)
            #pragma unroll
            for (int ot = 0; ot < 4; ot++)
                #pragma unroll
                for (int i = 0; i < 4; i++) hacc[mt][ot][i] = 0.0f;

        LOADX(0, 0); LOADW1(0, hcI, 0); CP_COMMIT();
        LOADX(1, 1); LOADW1(1, hcI, 1); CP_COMMIT();

        for (int t = 0; t < 8; t++) {
            const int s = t % N_STG;
            if (t < 7) { CP_WAIT(1); } else { CP_WAIT(0); }
            __syncthreads();   // stage s visible to all threads
            if (t + 2 < 8) {
                const int s2 = (t + 2) % N_STG;
                LOADX(t + 2, s2); LOADW1(t + 2, hcI, s2); CP_COMMIT();
            }
            const uint32_t xa = sb + XS_OFF + s * XSB + xa_off;
            const uint32_t wa = sb + WS_OFF + s * WSB + wb_off;
            MMA_STEP(hacc, xa, 16*XROW, wa, 16*XROW, 0);
            MMA_STEP(hacc, xa, 16*XROW, wa, 16*XROW, 32);
            MMA_STEP(hacc, xa, 16*XROW, wa, 16*XROW, 64);
            MMA_STEP(hacc, xa, 16*XROW, wa, 16*XROW, 96);
        }
        __syncthreads();   // phase-A reads done; ws/hs free to overwrite

        // prefetch both phase-B k64 tiles (stage 0,1) during GELU
        LOADW2(0, hcI, 0); CP_COMMIT();
        LOADW2(1, hcI, 1); CP_COMMIT();

        // ========== GELU: hacc -> hs (fp16) ==========
        #pragma unroll
        for (int mt = 0; mt < 2; mt++) {
            #pragma unroll
            for (int ot = 0; ot < 4; ot++) {
                int r0 = m0w + mt * 16 + g;
                int c  = n0w + ot * 8 + 2 * tig;
                __half2 lo = __floats2half2_rn(gelu_exact(hacc[mt][ot][0]),
                                               gelu_exact(hacc[mt][ot][1]));
                __half2 hi = __floats2half2_rn(gelu_exact(hacc[mt][ot][2]),
                                               gelu_exact(hacc[mt][ot][3]));
                *(__half2*)(smem + HS_OFF + r0 * HROW + c * 2)       = lo;
                *(__half2*)(smem + HS_OFF + (r0 + 8) * HROW + c * 2) = hi;
            }
        }
        CP_WAIT(0);        // this thread's W2 copies done
        __syncthreads();   // hs + all threads' W2 copies visible

        // ========== Phase B: out += gelu(hidden) @ W2chunk (2 k64-tiles, no waits) ==========
        #pragma unroll
        for (int t = 0; t < 2; t++) {
            const uint32_t ha = sb + ha_off + t * 128;
            const uint32_t wa = sb + WS_OFF + t * WSB + wb_off;
            MMA_STEP(oacc, ha, 16*HROW, wa, 16*XROW, 0);
            MMA_STEP(oacc, ha, 16*HROW, wa, 16*XROW, 32);
            MMA_STEP(oacc, ha, 16*HROW, wa, 16*XROW, 64);
            MMA_STEP(oacc, ha, 16*HROW, wa, 16*XROW, 96);
        }
        __syncthreads();   // phase-B MMAs done before next hc overwrites ws/hs
    }

    // ========== Epilogue: out[b][n][o][e], e innermost ==========
    #pragma unroll
    for (int mt = 0; mt < 2; mt++) {
        #pragma unroll
        for (int ot = 0; ot < 4; ot++) {
            int n_row = n0 + m0w + mt * 16 + g;
            int ocol  = n0w + ot * 8 + 2 * tig;
            size_t base = (((size_t)b * NSEQ + n_row) * ODIM + ocol) * NEXP + e;
            out[base]                                  = oacc[mt][ot][0];
            out[base + NEXP]                           = oacc[mt][ot][1];
            out[base + (size_t)8 * ODIM * NEXP]        = oacc[mt][ot][2];
            out[base + (size_t)8 * ODIM * NEXP + NEXP] = oacc[mt][ot][3];
        }
    }
}

// ---------------- launch ----------------
extern "C" void kernel_launch(void* const* d_in, const int* in_sizes, int n_in,
                              void* d_out, int out_size) {
    const float* x  = (const float*)d_in[0];
    const float* w1 = (const float*)d_in[1];
    const float* w2 = (const float*)d_in[2];
    float* out = (float*)d_out;
    (void)in_sizes; (void)n_in; (void)out_size;

    cudaFuncSetAttribute(experts_fused_kernel,
                         cudaFuncAttributeMaxDynamicSharedMemorySize, SMEM_BYTES);
    cudaFuncSetAttribute(experts_fused_kernel,
                         cudaFuncAttributePreferredSharedMemoryCarveout, 100);

    const int nx = BATCH * NSEQ * DIM / 4;
    prep_x<<<(nx + 255) / 256, 256>>>(x, nx);
    dim3 tb(32, 8, 1);
    prep_w1t<<<dim3(DIM/32, HID/32, NEXP), tb>>>(w1);
    prep_w2t<<<dim3(HID/32, ODIM/32, NEXP), tb>>>(w2);

    dim3 grid(NSEQ / BM, NEXP, BATCH);  // (32,16,4) = 2048 CTAs, 2/SM
    experts_fused_kernel<<<grid, 256, SMEM_BYTES>>>(out);
}

// round 14
// speedup vs baseline: 2.0946x; 1.0167x over previous
// R13: latency fix via straight-line ping-pong fragment double-buffering.
// (R11/R12's 2-D-array macro variant killed the container 4x; same schedule,
//  simpler codegen: plain arrays, no nested macro unrolls.)
#include <cuda_runtime.h>
#include <cuda_fp16.h>
#include <cstdint>

#define BATCH 4
#define NSEQ  2048
#define DIM   512
#define HID   512
#define NEXP  16
#define ODIM  128
#define BM    64
#define HC    128
#define KT    64

// fp16 staged copies
__device__ __half g_xh [BATCH * NSEQ * DIM];   // [b][n][d]
__device__ __half g_w1t[NEXP * HID * DIM];     // [e][h][d]  (N-major for GEMM1 B)
__device__ __half g_w2t[NEXP * ODIM * HID];    // [e][o][h]  (N-major for GEMM2 B)

// ---- SMEM layout (bytes) ----
#define XROW 144         // 64 halves + 16B pad: ldmatrix conflict-free
#define HROW 272         // 128 halves + 16B pad
#define XSB  (64 * XROW)     // 9216
#define WSB  (128 * XROW)    // 18432
#define N_STG 3
#define XS_OFF 0
#define WS_OFF (N_STG * XSB)              // 27648
#define HS_OFF (WS_OFF + N_STG * WSB)     // 82944
#define SMEM_BYTES (HS_OFF + BM * HROW + 64)   // 100416

__device__ __forceinline__ uint32_t smem_u32(const void* p) {
    uint32_t a;
    asm("{ .reg .u64 t; cvta.to.shared.u64 t, %1; cvt.u32.u64 %0, t; }" : "=r"(a) : "l"(p));
    return a;
}

#define CP16(dst, src) \
    asm volatile("cp.async.cg.shared.global [%0], [%1], 16;" :: "r"(dst), "l"(src) : "memory")
#define CP_COMMIT() asm volatile("cp.async.commit_group;" ::: "memory")
#define CP_WAIT(n)  asm volatile("cp.async.wait_group %0;" :: "n"(n) : "memory")

__device__ __forceinline__ void ldsm4(uint32_t& r0, uint32_t& r1, uint32_t& r2, uint32_t& r3,
                                      uint32_t addr) {
    asm volatile("ldmatrix.sync.aligned.m8n8.x4.shared.b16 {%0,%1,%2,%3}, [%4];"
        : "=r"(r0), "=r"(r1), "=r"(r2), "=r"(r3) : "r"(addr));
}

__device__ __forceinline__ void mma_f16(float c[4], const uint32_t a[4], uint32_t b0, uint32_t b1) {
    asm volatile(
        "mma.sync.aligned.m16n8k16.row.col.f32.f16.f16.f32 "
        "{%0,%1,%2,%3}, {%4,%5,%6,%7}, {%8,%9}, {%0,%1,%2,%3};"
        : "+f"(c[0]), "+f"(c[1]), "+f"(c[2]), "+f"(c[3])
        : "r"(a[0]), "r"(a[1]), "r"(a[2]), "r"(a[3]), "r"(b0), "r"(b1));
}

// load one k16 fragment set: A (2x m16) + B (2x n16 pair)
__device__ __forceinline__ void ld_frag(uint32_t* A, uint32_t* B,
                                        uint32_t abase, uint32_t astr,
                                        uint32_t bbase, uint32_t bstr) {
    ldsm4(A[0], A[1], A[2], A[3], abase);
    ldsm4(A[4], A[5], A[6], A[7], abase + astr);
    ldsm4(B[0], B[1], B[2], B[3], bbase);
    ldsm4(B[4], B[5], B[6], B[7], bbase + bstr);
}

// execute 8 MMAs for one k16 fragment set
__device__ __forceinline__ void exec_frag(float acc[2][4][4], const uint32_t* A, const uint32_t* B) {
    mma_f16(acc[0][0], A,     B[0], B[1]);
    mma_f16(acc[0][1], A,     B[2], B[3]);
    mma_f16(acc[0][2], A,     B[4], B[5]);
    mma_f16(acc[0][3], A,     B[6], B[7]);
    mma_f16(acc[1][0], A + 4, B[0], B[1]);
    mma_f16(acc[1][1], A + 4, B[2], B[3]);
    mma_f16(acc[1][2], A + 4, B[4], B[5]);
    mma_f16(acc[1][3], A + 4, B[6], B[7]);
}

__device__ __forceinline__ float gelu_exact(float v) {
    return 0.5f * v * (1.0f + erff(v * 0.70710678118654752440f));
}

// ---------------- prep kernels ----------------
__global__ void prep_x(const float* __restrict__ src, int n4) {
    int i = blockIdx.x * blockDim.x + threadIdx.x;
    if (i < n4) {
        float4 v = ((const float4*)src)[i];
        ((__half2*)g_xh)[i * 2]     = __floats2half2_rn(v.x, v.y);
        ((__half2*)g_xh)[i * 2 + 1] = __floats2half2_rn(v.z, v.w);
    }
}

__global__ void prep_w1t(const float* __restrict__ w1) {
    __shared__ float t[32][33];
    int d0 = blockIdx.x * 32, h0 = blockIdx.y * 32, e = blockIdx.z;
    const float* src = w1 + (size_t)e * DIM * HID;
    __half*      dst = g_w1t + (size_t)e * HID * DIM;
    int tx = threadIdx.x, ty = threadIdx.y;
    #pragma unroll
    for (int k = 0; k < 4; k++)
        t[ty + k*8][tx] = src[(size_t)(d0 + ty + k*8) * HID + h0 + tx];
    __syncthreads();
    #pragma unroll
    for (int k = 0; k < 4; k++)
        dst[(size_t)(h0 + ty + k*8) * DIM + d0 + tx] = __float2half_rn(t[tx][ty + k*8]);
}

__global__ void prep_w2t(const float* __restrict__ w2) {
    __shared__ float t[32][33];
    int h0 = blockIdx.x * 32, o0 = blockIdx.y * 32, e = blockIdx.z;
    const float* src = w2 + (size_t)e * HID * ODIM;
    __half*      dst = g_w2t + (size_t)e * ODIM * HID;
    int tx = threadIdx.x, ty = threadIdx.y;
    #pragma unroll
    for (int k = 0; k < 4; k++)
        t[ty + k*8][tx] = src[(size_t)(h0 + ty + k*8) * ODIM + o0 + tx];
    __syncthreads();
    #pragma unroll
    for (int k = 0; k < 4; k++)
        dst[(size_t)(o0 + ty + k*8) * HID + h0 + tx] = __float2half_rn(t[tx][ty + k*8]);
}

// ---------------- main fused kernel ----------------
extern __shared__ char smem[];

__global__ __launch_bounds__(256, 2)
void experts_fused_kernel(float* __restrict__ out)
{
    const uint32_t sb = smem_u32(smem);

    const int nt = blockIdx.x;   // 0..31
    const int e  = blockIdx.y;   // 0..15
    const int b  = blockIdx.z;   // 0..3
    const int n0 = nt * BM;

    const __half* xb  = g_xh  + (size_t)(b * NSEQ + n0) * DIM;
    const __half* w1e = g_w1t + (size_t)e * HID * DIM;
    const __half* w2e = g_w2t + (size_t)e * ODIM * HID;

    const int tid  = threadIdx.x;
    const int warp = tid >> 5;
    const int lane = tid & 31;
    const int g    = lane >> 2;
    const int tig  = lane & 3;
    const int wm   = warp >> 2;   // 0..1
    const int wn   = warp & 3;    // 0..3
    const int m0w  = wm * 32;
    const int n0w  = wn * 32;

    // cp.async coords
    const int cr0 = tid >> 3;          // base row (0..31)
    const int cc0 = (tid & 7) << 4;    // byte col (0..112)
    const int cs0 = (tid & 7) << 3;    // half col

    // ldmatrix per-lane offsets (relative to stage base)
    const uint32_t xa_off = (uint32_t)((m0w + (lane & 15)) * XROW + (lane >> 4) * 16);
    const uint32_t wb_off = (uint32_t)((n0w + (lane & 7) + ((lane >> 4) & 1) * 8) * XROW
                                       + ((lane >> 3) & 1) * 16);
    const uint32_t ha_off = (uint32_t)(HS_OFF + (m0w + (lane & 15)) * HROW + (lane >> 4) * 16);

    #define LOADX(t, s) do {                                                           \
        uint32_t xd = sb + XS_OFF + (s)*XSB;                                           \
        CP16(xd + (cr0)      * XROW + cc0, xb + (size_t)(cr0)      * DIM + (t)*KT + cs0); \
        CP16(xd + (cr0 + 32) * XROW + cc0, xb + (size_t)(cr0 + 32) * DIM + (t)*KT + cs0); \
    } while (0)
    #define LOADW1(t, hcI, s) do {                                                     \
        uint32_t wd = sb + WS_OFF + (s)*WSB;                                           \
        CP16(wd + (cr0)      * XROW + cc0, w1e + (size_t)((hcI)*HC + cr0)      * DIM + (t)*KT + cs0); \
        CP16(wd + (cr0 + 32) * XROW + cc0, w1e + (size_t)((hcI)*HC + cr0 + 32) * DIM + (t)*KT + cs0); \
        CP16(wd + (cr0 + 64) * XROW + cc0, w1e + (size_t)((hcI)*HC + cr0 + 64) * DIM + (t)*KT + cs0); \
        CP16(wd + (cr0 + 96) * XROW + cc0, w1e + (size_t)((hcI)*HC + cr0 + 96) * DIM + (t)*KT + cs0); \
    } while (0)
    #define LOADW2(t, hcI, s) do {                                                     \
        uint32_t wd = sb + WS_OFF + (s)*WSB;                                           \
        CP16(wd + (cr0)      * XROW + cc0, w2e + (size_t)(cr0)      * HID + (hcI)*HC + (t)*KT + cs0); \
        CP16(wd + (cr0 + 32) * XROW + cc0, w2e + (size_t)(cr0 + 32) * HID + (hcI)*HC + (t)*KT + cs0); \
        CP16(wd + (cr0 + 64) * XROW + cc0, w2e + (size_t)(cr0 + 64) * HID + (hcI)*HC + (t)*KT + cs0); \
        CP16(wd + (cr0 + 96) * XROW + cc0, w2e + (size_t)(cr0 + 96) * HID + (hcI)*HC + (t)*KT + cs0); \
    } while (0)

    // ping-pong fragment sets (plain 1-D arrays)
    uint32_t aP[8], bP[8];   // set P
    uint32_t aQ[8], bQ[8];   // set Q

    float oacc[2][4][4];
    #pragma unroll
    for (int mt = 0; mt < 2; mt++)
        #pragma unroll
        for (int ot = 0; ot < 4; ot++)
            #pragma unroll
            for (int i = 0; i < 4; i++) oacc[mt][ot][i] = 0.0f;

    for (int hcI = 0; hcI < HID / HC; hcI++) {
        // ========== Phase A: hidden[64,128] = X @ W1chunk, 8 k64-iters ==========
        float hacc[2][4][4];
        #pragma unroll
        for (int mt = 0; mt < 2; mt++)
            #pragma unroll
            for (int ot = 0; ot < 4; ot++)
                #pragma unroll
                for (int i = 0; i < 4; i++) hacc[mt][ot][i] = 0.0f;

        LOADX(0, 0); LOADW1(0, hcI, 0); CP_COMMIT();
        LOADX(1, 1); LOADW1(1, hcI, 1); CP_COMMIT();

        for (int t = 0; t < 8; t++) {
            const int s = t % N_STG;
            if (t < 7) { CP_WAIT(1); } else { CP_WAIT(0); }
            __syncthreads();   // stage s visible to all threads
            const uint32_t xa = sb + XS_OFF + s * XSB + xa_off;
            const uint32_t wa = sb + WS_OFF + s * WSB + wb_off;

            // head load (k16 #0), then cp.async prefetch covers its latency
            ld_frag(aP, bP, xa, 16*XROW, wa, 16*XROW);
            if (t + 2 < 8) {
                const int s2 = (t + 2) % N_STG;
                LOADX(t + 2, s2); LOADW1(t + 2, hcI, s2); CP_COMMIT();
            }
            // straight-line ping-pong: load next set while executing current
            ld_frag(aQ, bQ, xa + 32, 16*XROW, wa + 32, 16*XROW);
            exec_frag(hacc, aP, bP);
            ld_frag(aP, bP, xa + 64, 16*XROW, wa + 64, 16*XROW);
            exec_frag(hacc, aQ, bQ);
            ld_frag(aQ, bQ, xa + 96, 16*XROW, wa + 96, 16*XROW);
            exec_frag(hacc, aP, bP);
            exec_frag(hacc, aQ, bQ);
        }
        __syncthreads();   // phase-A reads done; ws/hs free to overwrite

        // prefetch both phase-B k64 tiles (stage 0,1) during GELU
        LOADW2(0, hcI, 0); CP_COMMIT();
        LOADW2(1, hcI, 1); CP_COMMIT();

        // ========== GELU: hacc -> hs (fp16) ==========
        #pragma unroll
        for (int mt = 0; mt < 2; mt++) {
            #pragma unroll
            for (int ot = 0; ot < 4; ot++) {
                int r0 = m0w + mt * 16 + g;
                int c  = n0w + ot * 8 + 2 * tig;
                __half2 lo = __floats2half2_rn(gelu_exact(hacc[mt][ot][0]),
                                               gelu_exact(hacc[mt][ot][1]));
                __half2 hi = __floats2half2_rn(gelu_exact(hacc[mt][ot][2]),
                                               gelu_exact(hacc[mt][ot][3]));
                *(__half2*)(smem + HS_OFF + r0 * HROW + c * 2)       = lo;
                *(__half2*)(smem + HS_OFF + (r0 + 8) * HROW + c * 2) = hi;
            }
        }
        CP_WAIT(0);        // this thread's W2 copies done
        __syncthreads();   // hs + all threads' W2 copies visible

        // ========== Phase B: out += gelu(hidden) @ W2chunk (2 k64 tiles) ==========
        for (int t2 = 0; t2 < 2; t2++) {
            const uint32_t ha = sb + ha_off + t2 * 128;
            const uint32_t wa = sb + WS_OFF + t2 * WSB + wb_off;
            ld_frag(aP, bP, ha,      16*HROW, wa,      16*XROW);
            ld_frag(aQ, bQ, ha + 32, 16*HROW, wa + 32, 16*XROW);
            exec_frag(oacc, aP, bP);
            ld_frag(aP, bP, ha + 64, 16*HROW, wa + 64, 16*XROW);
            exec_frag(oacc, aQ, bQ);
            ld_frag(aQ, bQ, ha + 96, 16*HROW, wa + 96, 16*XROW);
            exec_frag(oacc, aP, bP);
            exec_frag(oacc, aQ, bQ);
        }
        __syncthreads();   // phase-B MMAs done before next hc overwrites ws/hs
    }

    // ========== Epilogue: out[b][n][o][e], e innermost ==========
    #pragma unroll
    for (int mt = 0; mt < 2; mt++) {
        #pragma unroll
        for (int ot = 0; ot < 4; ot++) {
            int n_row = n0 + m0w + mt * 16 + g;
            int ocol  = n0w + ot * 8 + 2 * tig;
            size_t base = (((size_t)b * NSEQ + n_row) * ODIM + ocol) * NEXP + e;
            out[base]                                  = oacc[mt][ot][0];
            out[base + NEXP]                           = oacc[mt][ot][1];
            out[base + (size_t)8 * ODIM * NEXP]        = oacc[mt][ot][2];
            out[base + (size_t)8 * ODIM * NEXP + NEXP] = oacc[mt][ot][3];
        }
    }
}

// ---------------- launch ----------------
extern "C" void kernel_launch(void* const* d_in, const int* in_sizes, int n_in,
                              void* d_out, int out_size) {
    const float* x  = (const float*)d_in[0];
    const float* w1 = (const float*)d_in[1];
    const float* w2 = (const float*)d_in[2];
    float* out = (float*)d_out;
    (void)in_sizes; (void)n_in; (void)out_size;

    cudaFuncSetAttribute(experts_fused_kernel,
                         cudaFuncAttributeMaxDynamicSharedMemorySize, SMEM_BYTES);
    cudaFuncSetAttribute(experts_fused_kernel,
                         cudaFuncAttributePreferredSharedMemoryCarveout, 100);

    const int nx = BATCH * NSEQ * DIM / 4;
    prep_x<<<(nx + 255) / 256, 256>>>(x, nx);
    dim3 tb(32, 8, 1);
    prep_w1t<<<dim3(DIM/32, HID/32, NEXP), tb>>>(w1);
    prep_w2t<<<dim3(HID/32, ODIM/32, NEXP), tb>>>(w2);

    dim3 grid(NSEQ / BM, NEXP, BATCH);  // (32,16,4) = 2048 CTAs, 2/SM
    experts_fused_kernel<<<grid, 256, SMEM_BYTES>>>(out);
}

// round 16
// speedup vs baseline: 2.1553x; 1.0290x over previous
// R15: ILP-heavy reshape — 64x32 warp tiles (16 independent HMMA per k16 step,
// 6 LDSM per step), 8 warps/CTA, 1 CTA/SM, regs ~200. R13 pipeline machinery.
#include <cuda_runtime.h>
#include <cuda_fp16.h>
#include <cstdint>

#define BATCH 4
#define NSEQ  2048
#define DIM   512
#define HID   512
#define NEXP  16
#define ODIM  128
#define BM    128
#define HC    128
#define KT    64

// fp16 staged copies
__device__ __half g_xh [BATCH * NSEQ * DIM];   // [b][n][d]
__device__ __half g_w1t[NEXP * HID * DIM];     // [e][h][d]  (N-major for GEMM1 B)
__device__ __half g_w2t[NEXP * ODIM * HID];    // [e][o][h]  (N-major for GEMM2 B)

// ---- SMEM layout (bytes) ----
#define XROW 144                  // 64 halves + 16B pad
#define HROW 272                  // 128 halves + 16B pad
#define XSB  (128 * XROW)         // 18432 (x stage: 128 rows)
#define WSB  (128 * XROW)         // 18432 (w stage: 128 rows)
#define N_STG 3
#define XS_OFF 0
#define WS_OFF (N_STG * XSB)              // 55296
#define HS_OFF (WS_OFF + N_STG * WSB)     // 110592
#define SMEM_BYTES (HS_OFF + BM * HROW + 64)   // 145472

__device__ __forceinline__ uint32_t smem_u32(const void* p) {
    uint32_t a;
    asm("{ .reg .u64 t; cvta.to.shared.u64 t, %1; cvt.u32.u64 %0, t; }" : "=r"(a) : "l"(p));
    return a;
}

#define CP16(dst, src) \
    asm volatile("cp.async.cg.shared.global [%0], [%1], 16;" :: "r"(dst), "l"(src) : "memory")
#define CP_COMMIT() asm volatile("cp.async.commit_group;" ::: "memory")
#define CP_WAIT(n)  asm volatile("cp.async.wait_group %0;" :: "n"(n) : "memory")

__device__ __forceinline__ void ldsm4(uint32_t& r0, uint32_t& r1, uint32_t& r2, uint32_t& r3,
                                      uint32_t addr) {
    asm volatile("ldmatrix.sync.aligned.m8n8.x4.shared.b16 {%0,%1,%2,%3}, [%4];"
        : "=r"(r0), "=r"(r1), "=r"(r2), "=r"(r3) : "r"(addr));
}

__device__ __forceinline__ void mma_f16(float c[4], const uint32_t a[4], uint32_t b0, uint32_t b1) {
    asm volatile(
        "mma.sync.aligned.m16n8k16.row.col.f32.f16.f16.f32 "
        "{%0,%1,%2,%3}, {%4,%5,%6,%7}, {%8,%9}, {%0,%1,%2,%3};"
        : "+f"(c[0]), "+f"(c[1]), "+f"(c[2]), "+f"(c[3])
        : "r"(a[0]), "r"(a[1]), "r"(a[2]), "r"(a[3]), "r"(b0), "r"(b1));
}

// load one k16 fragment set: A = 4 m16 tiles (64 rows), B = 2 n16-pairs (32 n-rows)
__device__ __forceinline__ void ld_frags(uint32_t* A, uint32_t* B,
                                         uint32_t abase, uint32_t arstr,
                                         uint32_t bbase, uint32_t brstr) {
    ldsm4(A[0],  A[1],  A[2],  A[3],  abase);
    ldsm4(A[4],  A[5],  A[6],  A[7],  abase + arstr);
    ldsm4(A[8],  A[9],  A[10], A[11], abase + 2 * arstr);
    ldsm4(A[12], A[13], A[14], A[15], abase + 3 * arstr);
    ldsm4(B[0],  B[1],  B[2],  B[3],  bbase);
    ldsm4(B[4],  B[5],  B[6],  B[7],  bbase + brstr);
}

// 16 independent HMMAs (4 m16 x 4 n8)
__device__ __forceinline__ void exec_frags(float acc[4][4][4], const uint32_t* A, const uint32_t* B) {
    #pragma unroll
    for (int mt = 0; mt < 4; mt++) {
        mma_f16(acc[mt][0], A + 4 * mt, B[0], B[1]);
        mma_f16(acc[mt][1], A + 4 * mt, B[2], B[3]);
        mma_f16(acc[mt][2], A + 4 * mt, B[4], B[5]);
        mma_f16(acc[mt][3], A + 4 * mt, B[6], B[7]);
    }
}

__device__ __forceinline__ float gelu_exact(float v) {
    return 0.5f * v * (1.0f + erff(v * 0.70710678118654752440f));
}

// ---------------- prep kernels ----------------
__global__ void prep_x(const float* __restrict__ src, int n4) {
    int i = blockIdx.x * blockDim.x + threadIdx.x;
    if (i < n4) {
        float4 v = ((const float4*)src)[i];
        ((__half2*)g_xh)[i * 2]     = __floats2half2_rn(v.x, v.y);
        ((__half2*)g_xh)[i * 2 + 1] = __floats2half2_rn(v.z, v.w);
    }
}

__global__ void prep_w1t(const float* __restrict__ w1) {
    __shared__ float t[32][33];
    int d0 = blockIdx.x * 32, h0 = blockIdx.y * 32, e = blockIdx.z;
    const float* src = w1 + (size_t)e * DIM * HID;
    __half*      dst = g_w1t + (size_t)e * HID * DIM;
    int tx = threadIdx.x, ty = threadIdx.y;
    #pragma unroll
    for (int k = 0; k < 4; k++)
        t[ty + k*8][tx] = src[(size_t)(d0 + ty + k*8) * HID + h0 + tx];
    __syncthreads();
    #pragma unroll
    for (int k = 0; k < 4; k++)
        dst[(size_t)(h0 + ty + k*8) * DIM + d0 + tx] = __float2half_rn(t[tx][ty + k*8]);
}

__global__ void prep_w2t(const float* __restrict__ w2) {
    __shared__ float t[32][33];
    int h0 = blockIdx.x * 32, o0 = blockIdx.y * 32, e = blockIdx.z;
    const float* src = w2 + (size_t)e * HID * ODIM;
    __half*      dst = g_w2t + (size_t)e * ODIM * HID;
    int tx = threadIdx.x, ty = threadIdx.y;
    #pragma unroll
    for (int k = 0; k < 4; k++)
        t[ty + k*8][tx] = src[(size_t)(h0 + ty + k*8) * ODIM + o0 + tx];
    __syncthreads();
    #pragma unroll
    for (int k = 0; k < 4; k++)
        dst[(size_t)(o0 + ty + k*8) * HID + h0 + tx] = __float2half_rn(t[tx][ty + k*8]);
}

// ---------------- main fused kernel ----------------
extern __shared__ char smem[];

__global__ __launch_bounds__(256, 1)
void experts_fused_kernel(float* __restrict__ out)
{
    const uint32_t sb = smem_u32(smem);

    const int nt = blockIdx.x;   // 0..15
    const int e  = blockIdx.y;   // 0..15
    const int b  = blockIdx.z;   // 0..3
    const int n0 = nt * BM;

    const __half* xb  = g_xh  + (size_t)(b * NSEQ + n0) * DIM;
    const __half* w1e = g_w1t + (size_t)e * HID * DIM;
    const __half* w2e = g_w2t + (size_t)e * ODIM * HID;

    const int tid  = threadIdx.x;
    const int warp = tid >> 5;
    const int lane = tid & 31;
    const int g    = lane >> 2;
    const int tig  = lane & 3;
    const int wm   = warp >> 2;   // 0..1
    const int wn   = warp & 3;    // 0..3
    const int m0w  = wm * 64;     // 64-row warp tile
    const int n0w  = wn * 32;     // 32-col warp tile

    // cp.async coords: 16B chunks; 128-row x 64-half tile = 1024 chunks = 4/thread
    const int cr0 = tid >> 3;          // base row (0..31), +32/64/96
    const int cc0 = (tid & 7) << 4;    // byte col (0..112)
    const int cs0 = (tid & 7) << 3;    // half col

    // ldmatrix per-lane offsets (relative to stage base)
    const uint32_t xa_off = (uint32_t)((m0w + (lane & 15)) * XROW + (lane >> 4) * 16);
    const uint32_t wb_off = (uint32_t)((n0w + (lane & 7) + ((lane >> 4) & 1) * 8) * XROW
                                       + ((lane >> 3) & 1) * 16);
    const uint32_t ha_off = (uint32_t)(HS_OFF + (m0w + (lane & 15)) * HROW + (lane >> 4) * 16);

    #define LOADX(t, s) do {                                                           \
        uint32_t xd = sb + XS_OFF + (s)*XSB;                                           \
        CP16(xd + (cr0)      * XROW + cc0, xb + (size_t)(cr0)      * DIM + (t)*KT + cs0); \
        CP16(xd + (cr0 + 32) * XROW + cc0, xb + (size_t)(cr0 + 32) * DIM + (t)*KT + cs0); \
        CP16(xd + (cr0 + 64) * XROW + cc0, xb + (size_t)(cr0 + 64) * DIM + (t)*KT + cs0); \
        CP16(xd + (cr0 + 96) * XROW + cc0, xb + (size_t)(cr0 + 96) * DIM + (t)*KT + cs0); \
    } while (0)
    #define LOADW1(t, hcI, s) do {                                                     \
        uint32_t wd = sb + WS_OFF + (s)*WSB;                                           \
        CP16(wd + (cr0)      * XROW + cc0, w1e + (size_t)((hcI)*HC + cr0)      * DIM + (t)*KT + cs0); \
        CP16(wd + (cr0 + 32) * XROW + cc0, w1e + (size_t)((hcI)*HC + cr0 + 32) * DIM + (t)*KT + cs0); \
        CP16(wd + (cr0 + 64) * XROW + cc0, w1e + (size_t)((hcI)*HC + cr0 + 64) * DIM + (t)*KT + cs0); \
        CP16(wd + (cr0 + 96) * XROW + cc0, w1e + (size_t)((hcI)*HC + cr0 + 96) * DIM + (t)*KT + cs0); \
    } while (0)
    #define LOADW2(t, hcI, s) do {                                                     \
        uint32_t wd = sb + WS_OFF + (s)*WSB;                                           \
        CP16(wd + (cr0)      * XROW + cc0, w2e + (size_t)(cr0)      * HID + (hcI)*HC + (t)*KT + cs0); \
        CP16(wd + (cr0 + 32) * XROW + cc0, w2e + (size_t)(cr0 + 32) * HID + (hcI)*HC + (t)*KT + cs0); \
        CP16(wd + (cr0 + 64) * XROW + cc0, w2e + (size_t)(cr0 + 64) * HID + (hcI)*HC + (t)*KT + cs0); \
        CP16(wd + (cr0 + 96) * XROW + cc0, w2e + (size_t)(cr0 + 96) * HID + (hcI)*HC + (t)*KT + cs0); \
    } while (0)

    // ping-pong fragment sets
    uint32_t aP[16], bP[8];
    uint32_t aQ[16], bQ[8];

    float oacc[4][4][4];
    #pragma unroll
    for (int mt = 0; mt < 4; mt++)
        #pragma unroll
        for (int ot = 0; ot < 4; ot++)
            #pragma unroll
            for (int i = 0; i < 4; i++) oacc[mt][ot][i] = 0.0f;

    for (int hcI = 0; hcI < HID / HC; hcI++) {
        // ========== Phase A: hidden[128,128] = X @ W1chunk, 8 k64-iters ==========
        float hacc[4][4][4];
        #pragma unroll
        for (int mt = 0; mt < 4; mt++)
            #pragma unroll
            for (int ot = 0; ot < 4; ot++)
                #pragma unroll
                for (int i = 0; i < 4; i++) hacc[mt][ot][i] = 0.0f;

        LOADX(0, 0); LOADW1(0, hcI, 0); CP_COMMIT();
        LOADX(1, 1); LOADW1(1, hcI, 1); CP_COMMIT();

        for (int t = 0; t < 8; t++) {
            const int s = t % N_STG;
            if (t < 7) { CP_WAIT(1); } else { CP_WAIT(0); }
            __syncthreads();   // stage s visible to all threads
            const uint32_t xa = sb + XS_OFF + s * XSB + xa_off;
            const uint32_t wa = sb + WS_OFF + s * WSB + wb_off;

            // head load (k16 #0); cp.async prefetch issued under its latency
            ld_frags(aP, bP, xa, 16*XROW, wa, 16*XROW);
            if (t + 2 < 8) {
                const int s2 = (t + 2) % N_STG;
                LOADX(t + 2, s2); LOADW1(t + 2, hcI, s2); CP_COMMIT();
            }
            // ping-pong: load next k16 set while executing current
            ld_frags(aQ, bQ, xa + 32, 16*XROW, wa + 32, 16*XROW);
            exec_frags(hacc, aP, bP);
            ld_frags(aP, bP, xa + 64, 16*XROW, wa + 64, 16*XROW);
            exec_frags(hacc, aQ, bQ);
            ld_frags(aQ, bQ, xa + 96, 16*XROW, wa + 96, 16*XROW);
            exec_frags(hacc, aP, bP);
            exec_frags(hacc, aQ, bQ);
        }
        __syncthreads();   // phase-A reads done; ws/hs free to overwrite

        // prefetch both phase-B k64 tiles (stage 0,1) during GELU
        LOADW2(0, hcI, 0); CP_COMMIT();
        LOADW2(1, hcI, 1); CP_COMMIT();

        // ========== GELU: hacc -> hs (fp16) ==========
        #pragma unroll
        for (int mt = 0; mt < 4; mt++) {
            #pragma unroll
            for (int ot = 0; ot < 4; ot++) {
                int r0 = m0w + mt * 16 + g;
                int c  = n0w + ot * 8 + 2 * tig;
                __half2 lo = __floats2half2_rn(gelu_exact(hacc[mt][ot][0]),
                                               gelu_exact(hacc[mt][ot][1]));
                __half2 hi = __floats2half2_rn(gelu_exact(hacc[mt][ot][2]),
                                               gelu_exact(hacc[mt][ot][3]));
                *(__half2*)(smem + HS_OFF + r0 * HROW + c * 2)       = lo;
                *(__half2*)(smem + HS_OFF + (r0 + 8) * HROW + c * 2) = hi;
            }
        }
        CP_WAIT(0);        // this thread's W2 copies done
        __syncthreads();   // hs + all threads' W2 copies visible

        // ========== Phase B: out += gelu(hidden) @ W2chunk (2 k64 tiles) ==========
        for (int t2 = 0; t2 < 2; t2++) {
            const uint32_t ha = sb + ha_off + t2 * 128;
            const uint32_t wa = sb + WS_OFF + t2 * WSB + wb_off;
            ld_frags(aP, bP, ha,      16*HROW, wa,      16*XROW);
            ld_frags(aQ, bQ, ha + 32, 16*HROW, wa + 32, 16*XROW);
            exec_frags(oacc, aP, bP);
            ld_frags(aP, bP, ha + 64, 16*HROW, wa + 64, 16*XROW);
            exec_frags(oacc, aQ, bQ);
            ld_frags(aQ, bQ, ha + 96, 16*HROW, wa + 96, 16*XROW);
            exec_frags(oacc, aP, bP);
            exec_frags(oacc, aQ, bQ);
        }
        __syncthreads();   // phase-B MMAs done before next hc overwrites ws/hs
    }

    // ========== Epilogue: out[b][n][o][e], e innermost ==========
    #pragma unroll
    for (int mt = 0; mt < 4; mt++) {
        #pragma unroll
        for (int ot = 0; ot < 4; ot++) {
            int n_row = n0 + m0w + mt * 16 + g;
            int ocol  = n0w + ot * 8 + 2 * tig;
            size_t base = (((size_t)b * NSEQ + n_row) * ODIM + ocol) * NEXP + e;
            out[base]                                  = oacc[mt][ot][0];
            out[base + NEXP]                           = oacc[mt][ot][1];
            out[base + (size_t)8 * ODIM * NEXP]        = oacc[mt][ot][2];
            out[base + (size_t)8 * ODIM * NEXP + NEXP] = oacc[mt][ot][3];
        }
    }
}

// ---------------- launch ----------------
extern "C" void kernel_launch(void* const* d_in, const int* in_sizes, int n_in,
                              void* d_out, int out_size) {
    const float* x  = (const float*)d_in[0];
    const float* w1 = (const float*)d_in[1];
    const float* w2 = (const float*)d_in[2];
    float* out = (float*)d_out;
    (void)in_sizes; (void)n_in; (void)out_size;

    cudaFuncSetAttribute(experts_fused_kernel,
                         cudaFuncAttributeMaxDynamicSharedMemorySize, SMEM_BYTES);
    cudaFuncSetAttribute(experts_fused_kernel,
                         cudaFuncAttributePreferredSharedMemoryCarveout, 100);

    const int nx = BATCH * NSEQ * DIM / 4;
    prep_x<<<(nx + 255) / 256, 256>>>(x, nx);
    dim3 tb(32, 8, 1);
    prep_w1t<<<dim3(DIM/32, HID/32, NEXP), tb>>>(w1);
    prep_w2t<<<dim3(HID/32, ODIM/32, NEXP), tb>>>(w2);

    dim3 grid(NSEQ / BM, NEXP, BATCH);  // (16,16,4) = 1024 CTAs, 1/SM
    experts_fused_kernel<<<grid, 256, SMEM_BYTES>>>(out);
}